// round 15
// baseline (speedup 1.0000x reference)
#include <cuda_runtime.h>
#include <cuda_bf16.h>
#include <math_constants.h>

#define BQ 64
#define LQ 32
#define BD 128
#define LD 192
#define TOK_D 32
#define CLS_D 768

#define DSPLIT 4
#define DOCS_PER 32                    // BD / DSPLIT
#define SCAN_TOK (DOCS_PER * LD)       // 6144 tokens per block
#define SCAN_I4 (SCAN_TOK / 4)         // 1536 int4

// Order-preserving uint encoding of float; 0 is never produced for a real
// float, so slot==0 means "never written".
__device__ __forceinline__ unsigned enc_f(float f) {
    unsigned b = __float_as_uint(f);
    return (b & 0x80000000u) ? ~b : (b | 0x80000000u);
}
__device__ __forceinline__ float dec_f(unsigned u) {
    return __uint_as_float((u & 0x80000000u) ? (u ^ 0x80000000u) : ~u);
}
__device__ __forceinline__ unsigned hash_id(unsigned id) {
    return (id * 0x9E3779B1u) >> 24;   // 0..255
}

// ---------------------------------------------------------------------------
// Block = (query q, slice of 32 docs). grid = 64*4 = 256, 512 threads.
//  pre:   prefetch qmask/qid/scan-ids/qcls row; stage qtok row tile; init
//  build: hash of the 32 query ids (t<32)
//  scan:  6144 doc tokens, coalesced; probe 256-slot table (1 LDS, mostly
//         empty); rare match -> 32-dim dot (smem x L2) -> atomicMax slot
//  comb:  warp w covers docs {2w, 2w+1}; mask/SEP + all-match corner + CLS
// ---------------------------------------------------------------------------
__global__ __launch_bounds__(512) void coil_qscan_kernel(
    const float* __restrict__ qtok,   // [BQ, LQ, TOK_D]
    const float* __restrict__ dtok,   // [BD, LD, TOK_D]
    const float* __restrict__ qcls,   // [BQ, CLS_D]
    const float* __restrict__ dcls,   // [BD, CLS_D]
    const int*   __restrict__ qids,   // [BQ, LQ]
    const int*   __restrict__ dids,   // [BD, LD]
    const int*   __restrict__ qmask,  // [BQ, LQ]
    float*       __restrict__ out)    // [BQ, BD]
{
    __shared__ float    qtokS[LQ * TOK_D];     // 4 KB
    __shared__ unsigned slots[256];            // head i per bucket, 0xFF empty
    __shared__ unsigned ent[LQ];               // (id << 8) | next_i
    __shared__ unsigned slot32[DOCS_PER * LQ]; // [dl][i] enc-float max, 4 KB
    __shared__ unsigned firstidS[DOCS_PER];
    __shared__ int      diffS[DOCS_PER];

    const int bx   = blockIdx.x;
    const int q    = bx >> 2;
    const int d0   = (bx & 3) * DOCS_PER;
    const int t    = threadIdx.x;
    const int w    = t >> 5;
    const int lane = t & 31;

    // ---- prefetch (pure LDG, high MLP) ----
    const int      qm      = qmask[q * LQ + lane];
    const unsigned qidlane = (unsigned)qids[q * LQ + lane];

    int4 sc[3];
    const int4* dbase = (const int4*)(dids + d0 * LD);
#pragma unroll
    for (int r = 0; r < 3; r++) sc[r] = dbase[t + 512 * r];

    float4 av[6];                               // qcls row, lane covers 24 dims
    const float4* qcp = (const float4*)(qcls + q * CLS_D);
#pragma unroll
    for (int c = 0; c < 6; c++) av[c] = qcp[c * 32 + lane];

    // ---- init + staging ----
    if (t < 256) {
        ((float4*)qtokS)[t] = ((const float4*)(qtok + q * LQ * TOK_D))[t];
        slots[t] = 0xFFu;
    }
    slot32[t] = 0u;
    slot32[t + 512] = 0u;
    if (t < DOCS_PER) {
        diffS[t] = 0;
        firstidS[t] = (unsigned)dids[(d0 + t) * LD];
    }
    __syncthreads();

    // ---- build hash of 32 query ids (entry index == query pos i) ----
    if (t < LQ) {
        const unsigned id = (unsigned)qids[q * LQ + t];
        const unsigned old = atomicExch(&slots[hash_id(id)], (unsigned)t);
        ent[t] = (id << 8) | (old & 0xFFu);
    }
    __syncthreads();

    // ---- scan 6144 doc tokens ----
#pragma unroll
    for (int r = 0; r < 3; r++) {
        const int base = (t + 512 * r) * 4;
        const unsigned idv[4] = {(unsigned)sc[r].x, (unsigned)sc[r].y,
                                 (unsigned)sc[r].z, (unsigned)sc[r].w};
#pragma unroll
        for (int c = 0; c < 4; c++) {
            const unsigned id  = idv[c];
            const int      tok = base + c;
            const int      dl  = tok / LD;
            const int      j   = tok - dl * LD;
            if (id != firstidS[dl]) diffS[dl] = 1;
            unsigned cur = slots[hash_id(id)];
            while (cur != 0xFFu) {
                const unsigned e = ent[cur];
                if ((e >> 8) == id) {
                    const float4* qr = (const float4*)(qtokS + cur * TOK_D);
                    const float4* dr =
                        (const float4*)(dtok + ((d0 + dl) * LD + j) * TOK_D);
                    float s = 0.0f;
#pragma unroll
                    for (int e2 = 0; e2 < TOK_D / 4; e2++) {
                        const float4 a = qr[e2];
                        const float4 b = dr[e2];
                        s += a.x * b.x + a.y * b.y + a.z * b.z + a.w * b.w;
                    }
                    atomicMax(&slot32[dl * LQ + cur], enc_f(s));
                }
                cur = e & 0xFFu;
            }
        }
    }
    __syncthreads();

    // ---- combine: warp w handles docs dl = 2w, 2w+1 ----
    const int tot = __reduce_add_sync(0xFFFFFFFFu, qm);
    const float qmf = (lane == tot - 1) ? 0.0f : (float)qm;

    float v[2];
#pragma unroll
    for (int kk = 0; kk < 2; kk++) {
        const int dl = w * 2 + kk;
        const int d  = d0 + dl;

        const unsigned slot = slot32[dl * LQ + lane];
        float val;
        if (slot == 0u) {
            val = 0.0f;                      // no match: row of zeros -> max 0
        } else {
            const float mm = dec_f(slot);
            // all 192 doc tokens equal this qid -> no zero participates in max
            const bool full = (diffS[dl] == 0) && (qidlane == firstidS[dl]);
            val = full ? mm : fmaxf(mm, 0.0f);
        }
        float acc = (lane >= 1) ? val * qmf : 0.0f;

        const float4* dcp = (const float4*)(dcls + d * CLS_D);
#pragma unroll
        for (int c = 0; c < 6; c++) {
            const float4 b = dcp[c * 32 + lane];
            acc += av[c].x * b.x + av[c].y * b.y + av[c].z * b.z + av[c].w * b.w;
        }
        v[kk] = acc;
    }
#pragma unroll
    for (int s = 16; s; s >>= 1) {
        v[0] += __shfl_xor_sync(0xFFFFFFFFu, v[0], s);
        v[1] += __shfl_xor_sync(0xFFFFFFFFu, v[1], s);
    }
    if (lane == 0) {
        out[q * BD + d0 + w * 2 + 0] = v[0];
        out[q * BD + d0 + w * 2 + 1] = v[1];
    }
}

// ---------------------------------------------------------------------------
extern "C" void kernel_launch(void* const* d_in, const int* in_sizes, int n_in,
                              void* d_out, int out_size) {
    const float* qtok  = (const float*)d_in[0];
    const float* dtok  = (const float*)d_in[1];
    const float* qcls  = (const float*)d_in[2];
    const float* dcls  = (const float*)d_in[3];
    const int*   qids  = (const int*)d_in[4];
    const int*   dids  = (const int*)d_in[5];
    const int*   qmask = (const int*)d_in[6];
    float* out = (float*)d_out;

    coil_qscan_kernel<<<BQ * DSPLIT, 512>>>(qtok, dtok, qcls, dcls,
                                            qids, dids, qmask, out);
}

// round 16
// speedup vs baseline: 1.8786x; 1.8786x over previous
#include <cuda_runtime.h>
#include <cuda_bf16.h>
#include <math_constants.h>

#define BQ 64
#define LQ 32
#define BD 128
#define LD 192
#define TOK_D 32
#define CLS_D 768

#define QH 32            // queries per block (half of BQ)
#define NE 1024          // hash entries per block = QH * LQ
#define HSH 2048         // hash slots (load factor 0.5)
#define MCAP 2048        // match-record capacity

// Order-preserving uint encoding of float; never produces 0 for a real float,
// so slot==0 means "never written".
__device__ __forceinline__ unsigned enc_f(float f) {
    unsigned b = __float_as_uint(f);
    return (b & 0x80000000u) ? ~b : (b | 0x80000000u);
}
__device__ __forceinline__ float dec_f(unsigned u) {
    return __uint_as_float((u & 0x80000000u) ? (u ^ 0x80000000u) : ~u);
}
__device__ __forceinline__ unsigned hash_id(unsigned id) {
    return (id * 0x9E3779B1u) >> 21;   // 0..2047
}

// ---------------------------------------------------------------------------
// Block = (doc d, half of the queries). grid = 128*2 = 256, 256 threads.
//   prefetch: qids/qmask (warp-owned), build-ids, doc ids, dcls row   [LDG]
//   build:    hash of 1024 query (q,i) ids, 4 atomicExch/thread       [ATOMS]
//   probe:    192 threads walk chains, EMIT records only (no dots)    [LDS]
//   (CLS dots by all threads overlap the probe tail)                  [LDG/FMA]
//   process:  all 256 threads: one record each -> 32-dim dot from L2
//             -> atomicMax into order-independent slot                [LDG]
//   combine:  warp w owns 4 queries: slots + mask/SEP + corner + CLS,
//             butterfly, store
// ---------------------------------------------------------------------------
__global__ __launch_bounds__(256) void coil_split_kernel(
    const float* __restrict__ qtok,   // [BQ, LQ, TOK_D]
    const float* __restrict__ dtok,   // [BD, LD, TOK_D]
    const float* __restrict__ qcls,   // [BQ, CLS_D]
    const float* __restrict__ dcls,   // [BD, CLS_D]
    const int*   __restrict__ qids,   // [BQ, LQ]
    const int*   __restrict__ dids,   // [BD, LD]
    const int*   __restrict__ qmask,  // [BQ, LQ]
    float*       __restrict__ out)    // [BQ, BD]
{
    __shared__ unsigned slots[HSH];    // 8 KB: head entry per bucket, 0xFFF empty
    __shared__ unsigned ent[NE];       // 4 KB: (id << 12) | next
    __shared__ unsigned mslot[NE];     // 4 KB: enc-float max per local (q,i)
    __shared__ unsigned mlist[MCAP];   // 8 KB: (entry << 8) | j
    __shared__ float    dclsS[CLS_D];  // 3 KB
    __shared__ int      mcountS, allsameS;

    const int bx    = blockIdx.x;
    const int d     = bx >> 1;
    const int qbase = (bx & 1) * QH;
    const int t     = threadIdx.x;
    const int w     = t >> 5;          // 0..7
    const int lane  = t & 31;

    // ---- prefetch (pure LDG, high MLP, no smem dependence) ----
    int qid4[4], qm4[4];
#pragma unroll
    for (int k = 0; k < 4; k++) {
        const int q = qbase + w * 4 + k;
        qid4[k] = qids[q * LQ + lane];
        qm4[k]  = qmask[q * LQ + lane];
    }
    unsigned bid[4];                   // ids for hash build (coalesced)
#pragma unroll
    for (int f = 0; f < 4; f++) bid[f] = (unsigned)qids[qbase * LQ + t + f * 256];

    unsigned myid = 0u;
    if (t < LD) myid = (unsigned)dids[d * LD + t];
    const unsigned d0id = (unsigned)dids[d * LD];   // uniform broadcast load

    if (t < CLS_D / 4)
        ((float4*)dclsS)[t] = ((const float4*)(dcls + d * CLS_D))[t];

    // ---- init ----
#pragma unroll
    for (int f = 0; f < 8; f++) slots[t + f * 256] = 0xFFFu;
#pragma unroll
    for (int f = 0; f < 4; f++) mslot[t + f * 256] = 0u;
    if (t == 0) { mcountS = 0; allsameS = 1; }
    __syncthreads();

    // ---- build hash (entry e == local q*32 + i) ----
#pragma unroll
    for (int f = 0; f < 4; f++) {
        const unsigned e = (unsigned)(t + f * 256);
        const unsigned old = atomicExch(&slots[hash_id(bid[f])], e);
        ent[e] = (bid[f] << 12) | (old & 0xFFFu);
    }
    if (t < LD && myid != d0id) allsameS = 0;
    __syncthreads();

    // ---- probe & emit (192 threads; records only, no dots in the walk) ----
    if (t < LD) {
        unsigned cur = slots[hash_id(myid)];
        while (cur != 0xFFFu) {
            const unsigned e = ent[cur];
            if ((e >> 12) == myid) {
                const int pos = atomicAdd(&mcountS, 1);
                if (pos < MCAP) mlist[pos] = (cur << 8) | (unsigned)t;
            }
            cur = e & 0xFFFu;
        }
    }

    // ---- CLS dots (all threads; overlaps probe tail) ----
    float4 bv[6];
#pragma unroll
    for (int c = 0; c < 6; c++) bv[c] = ((const float4*)dclsS)[c * 32 + lane];
    float cls4[4];
#pragma unroll
    for (int k = 0; k < 4; k++) {
        const int q = qbase + w * 4 + k;
        const float4* qc = (const float4*)(qcls + q * CLS_D);
        float acc = 0.0f;
#pragma unroll
        for (int c = 0; c < 6; c++) {
            const float4 a = qc[c * 32 + lane];
            acc += a.x * bv[c].x + a.y * bv[c].y + a.z * bv[c].z + a.w * bv[c].w;
        }
        cls4[k] = acc;
    }
    __syncthreads();

    // ---- process records (~39 expected; one thread each, L2 dots) ----
    const int mc = min(mcountS, MCAP);
    for (int r = t; r < mc; r += 256) {
        const unsigned rec = mlist[r];
        const unsigned e   = rec >> 8;          // local entry = q*32 + i
        const int      j   = (int)(rec & 0xFFu);
        const float4* qr = (const float4*)(qtok + (qbase * LQ + (int)e) * TOK_D);
        const float4* dr = (const float4*)(dtok + (d * LD + j) * TOK_D);
        float s = 0.0f;
#pragma unroll
        for (int e2 = 0; e2 < TOK_D / 4; e2++) {
            const float4 a = qr[e2];
            const float4 b = dr[e2];
            s += a.x * b.x + a.y * b.y + a.z * b.z + a.w * b.w;
        }
        atomicMax(&mslot[e], enc_f(s));
    }
    __syncthreads();

    // ---- combine: warp w owns queries qbase + 4w .. 4w+3 ----
    float v[4];
#pragma unroll
    for (int k = 0; k < 4; k++) {
        const int tot = __reduce_add_sync(0xFFFFFFFFu, qm4[k]);
        const float qmf = (lane == tot - 1) ? 0.0f : (float)qm4[k];

        const unsigned slot = mslot[(w * 4 + k) * LQ + lane];
        float val;
        if (slot == 0u) {
            val = 0.0f;                 // no match: row of zeros -> max is 0
        } else {
            const float mm = dec_f(slot);
            // all 192 doc tokens equal this qid -> no zero participates in max
            const bool full = (allsameS != 0) && ((unsigned)qid4[k] == d0id);
            val = full ? mm : fmaxf(mm, 0.0f);
        }
        v[k] = ((lane >= 1) ? val * qmf : 0.0f) + cls4[k];
    }
#pragma unroll
    for (int s = 16; s; s >>= 1) {
#pragma unroll
        for (int k = 0; k < 4; k++) v[k] += __shfl_xor_sync(0xFFFFFFFFu, v[k], s);
    }
    if (lane == 0) {
#pragma unroll
        for (int k = 0; k < 4; k++) out[(qbase + w * 4 + k) * BD + d] = v[k];
    }
}

// ---------------------------------------------------------------------------
extern "C" void kernel_launch(void* const* d_in, const int* in_sizes, int n_in,
                              void* d_out, int out_size) {
    const float* qtok  = (const float*)d_in[0];
    const float* dtok  = (const float*)d_in[1];
    const float* qcls  = (const float*)d_in[2];
    const float* dcls  = (const float*)d_in[3];
    const int*   qids  = (const int*)d_in[4];
    const int*   dids  = (const int*)d_in[5];
    const int*   qmask = (const int*)d_in[6];
    float* out = (float*)d_out;

    coil_split_kernel<<<2 * BD, 256>>>(qtok, dtok, qcls, dcls,
                                       qids, dids, qmask, out);
}